// round 10
// baseline (speedup 1.0000x reference)
#include <cuda_runtime.h>
#include <cstdint>

// GARCH(1,1) path generation — one thread per (n,d) scalar chain.
//
// R1 private rows: L1tex wavefront bound (302us). R3 CTA smem staging: 254us.
// R5 warp-autonomous rings: 204us. R6 CTA==warp (1024 CTAs): 195us, DRAM 71%,
// occ pinned at 10.3% (1024 warps). R7 coarser stages regressed; R8 clamp
// off-chain was neutral (chain already hidden). R9: exploit D=2 independence
// -> 65536 scalar chains, one thread each -> 2048 warps (13.8/SM), 2x the
// latency-hiding at identical traffic.
//
// per (n,d): sigma2_t = omega_d + sigma2_{t-1} * (alpha_d*z_{t-1}^2 + beta_d)
//            x_t = mu_d + sqrt(max(sigma2_t, 1e-12)) * z_t
// (sigma2 >= omega > 0 here, so the carried value needs no clamp; clamp only
//  feeds the sqrt.)

#define GARCH_N 32768
#define GARCH_T 2048
#define GARCH_D 2
#define ROW_BYTES (GARCH_T * GARCH_D * 4)   // 16384 bytes per chain-row (n)

#define CHN     16                 // n-chains per CTA (32 threads = 16n x 2d)
#define TC      16                 // timesteps per stage
#define CHUNK   (TC * GARCH_D * 4) // 128 bytes per n-chain per stage
#define NSTAGE  (GARCH_T / TC)     // 128 stages
#define DEPTH   5                  // input ring depth
#define NROUND  (CHN * 8 / 32)     // 4 cooperative 16B rounds per tile

#define TILE_W  (CHN * CHUNK)                    // 2 KB per tile
#define SMEM_BYTES (TILE_W * (DEPTH + 2))        // 5 in + 2 out = 14 KB

__device__ __forceinline__ float sqapx(float x) {
    float r; asm("sqrt.approx.f32 %0, %1;" : "=f"(r) : "f"(x)); return r;
}

// offset of (n-chain c, 16B-chunk j) within a 2KB tile.
// XOR-8 swizzle: conflict-free for the cooperative sweep (8 lanes, fixed c,
// j=lane&7) and for the compute sweep (fixed j; distinct c -> distinct banks,
// lane pairs read the same address = broadcast).
__device__ __forceinline__ int swz(int c, int j) {
    return c * CHUNK + ((j ^ (c & 7)) << 4);
}

__device__ __forceinline__ void cp_async16(char* smem_dst, const char* gsrc) {
    unsigned saddr = (unsigned)__cvta_generic_to_shared(smem_dst);
    asm volatile("cp.async.cg.shared.global [%0], [%1], 16;\n"
                 :: "r"(saddr), "l"(gsrc));
}
__device__ __forceinline__ void cp_commit() {
    asm volatile("cp.async.commit_group;\n");
}
__device__ __forceinline__ void cp_wait() {
    asm volatile("cp.async.wait_group %0;\n" :: "n"(DEPTH - 1));
}

__global__ void __launch_bounds__(32, 14)
garch_kernel(const float* __restrict__ z,
             const float* __restrict__ omega,
             const float* __restrict__ alpha,
             const float* __restrict__ beta,
             const float* __restrict__ mu,
             const float* __restrict__ sigma2_0,
             float* __restrict__ x)
{
    extern __shared__ char smem[];
    const int l  = threadIdx.x;             // lane
    const int cc = l >> 1;                  // compute: my n-chain (0..15)
    const int d  = l & 1;                   // compute: my dimension

    char* wbase = smem;
    char* outb0 = wbase + DEPTH * TILE_W;
    char* outb1 = outb0 + TILE_W;

    const size_t chain_base = (size_t)blockIdx.x * CHN;
    const char* zg = (const char*)z + chain_base * ROW_BYTES;
    char*       xg = (char*)x       + chain_base * ROW_BYTES;

    // cooperative mapping: round k (0..3): chunkid = l + 32k
    //   n-chain tc = chunkid>>3 ; 16B-chunk jj = l&7 (fixed per lane)
    // 8 consecutive lanes cover one chain's contiguous 128B (one line).
    const int jj = l & 7;

    // ---- prologue: fill DEPTH input tiles; group g <-> tile g ----
#pragma unroll
    for (int sp = 0; sp < DEPTH; sp++) {
        char* dst = wbase + sp * TILE_W;
#pragma unroll
        for (int k = 0; k < NROUND; k++) {
            int tc = (l + 32 * k) >> 3;
            cp_async16(dst + swz(tc, jj),
                       zg + (size_t)tc * ROW_BYTES + sp * CHUNK + jj * 16);
        }
        cp_commit();
    }

    // ---- scalar per-(n,d) recurrence state ----
    const float om = omega[d];
    const float al = alpha[d];
    const float be = beta[d];
    const float m  = mu[d];
    float s2 = sigma2_0[d];
    float fc = be;

    for (int s = 0; s < NSTAGE; s++) {
        // ---- prefetch tile s+DEPTH-1 into ring slot freed at iter s-1 ----
        if (s > 0) {
            const int sp = s + DEPTH - 1;
            if (sp < NSTAGE) {
                char* dst = wbase + (sp % DEPTH) * TILE_W;
#pragma unroll
                for (int k = 0; k < NROUND; k++) {
                    int tc = (l + 32 * k) >> 3;
                    cp_async16(dst + swz(tc, jj),
                               zg + (size_t)tc * ROW_BYTES + (size_t)sp * CHUNK + jj * 16);
                }
            }
            cp_commit();   // always commit: keeps group<->tile accounting exact
        }

        // ---- cooperative coalesced store of out tile s-1 ----
        if (s > 0) {
            const char* ob = ((s - 1) & 1) ? outb1 : outb0;
            const size_t tbase = (size_t)(s - 1) * CHUNK;
#pragma unroll
            for (int k = 0; k < NROUND; k++) {
                int tc = (l + 32 * k) >> 3;
                const float4 v = *(const float4*)(ob + swz(tc, jj));
                *(float4*)(xg + (size_t)tc * ROW_BYTES + tbase + jj * 16) = v;
            }
        }

        // Groups committed so far: DEPTH + s (tail commits may be empty and
        // complete instantly). pending<=DEPTH-1 => tile s complete.
        cp_wait();
        __syncwarp();   // cp.async data visible warp-wide

        // ---- compute 16 timesteps for this thread's (n,d) chain ----
        const char* ib = wbase + (s % DEPTH) * TILE_W;
        char* ob = (s & 1) ? outb1 : outb0;
#pragma unroll
        for (int j = 0; j < 8; j++) {
            // chunk j of my chain row: [z(2j,0), z(2j,1), z(2j+1,0), z(2j+1,1)]
            // lane pair (2cc, 2cc+1) reads the same address -> smem broadcast.
            const float4 za = *(const float4*)(ib + swz(cc, j));
            const float z0 = d ? za.y : za.x;   // t = 2j,   dim d
            const float z1 = d ? za.w : za.z;   // t = 2j+1, dim d

            // step t = 2j
            s2 = fmaf(s2, fc, om);              // whole serial chain
            const float c0 = fmaxf(s2, 1e-12f);
            fc = fmaf(al, z0 * z0, be);
            const float x0 = fmaf(sqapx(c0), z0, m);

            // step t = 2j+1
            s2 = fmaf(s2, fc, om);
            const float c1 = fmaxf(s2, 1e-12f);
            fc = fmaf(al, z1 * z1, be);
            const float x1 = fmaf(sqapx(c1), z1, m);

            // both values land inside 16B-chunk j of my chain's out row:
            //   byte (t&1)*8 + d*4 within the chunk
            char* base = ob + swz(cc, j);
            *(float*)(base + d * 4)     = x0;
            *(float*)(base + 8 + d * 4) = x1;
        }

        __syncwarp();   // out tile s complete before iter s+1 reads it
    }

    // ---- epilogue: store the final out tile ----
    {
        const char* ob = ((NSTAGE - 1) & 1) ? outb1 : outb0;
        const size_t tbase = (size_t)(NSTAGE - 1) * CHUNK;
#pragma unroll
        for (int k = 0; k < NROUND; k++) {
            int tc = (l + 32 * k) >> 3;
            const float4 v = *(const float4*)(ob + swz(tc, jj));
            *(float4*)(xg + (size_t)tc * ROW_BYTES + tbase + jj * 16) = v;
        }
    }
}

extern "C" void kernel_launch(void* const* d_in, const int* in_sizes, int n_in,
                              void* d_out, int out_size)
{
    const float* z        = (const float*)d_in[0];
    const float* omega    = (const float*)d_in[1];
    const float* alpha    = (const float*)d_in[2];
    const float* beta     = (const float*)d_in[3];
    const float* mu       = (const float*)d_in[4];
    const float* sigma2_0 = (const float*)d_in[5];
    float* x = (float*)d_out;

    cudaFuncSetAttribute(garch_kernel,
                         cudaFuncAttributeMaxDynamicSharedMemorySize, SMEM_BYTES);

    const int blocks = GARCH_N / CHN;   // 2048 single-warp CTAs
    garch_kernel<<<blocks, 32, SMEM_BYTES>>>(z, omega, alpha, beta, mu, sigma2_0, x);
}

// round 11
// speedup vs baseline: 1.0256x; 1.0256x over previous
#include <cuda_runtime.h>
#include <cstdint>

// GARCH(1,1) path generation — one thread per (n,d) scalar chain.
//
// R1 private rows: L1tex wavefront bound (302us). R3 CTA smem staging: 254us.
// R5 warp-autonomous rings: 204us. R6 CTA==warp (1024 CTAs): 195us, DRAM 71%,
// occ pinned at 10.3% (1024 warps). R7 coarser stages regressed; R8 clamp
// off-chain was neutral (chain already hidden). R9: exploit D=2 independence
// -> 65536 scalar chains, one thread each -> 2048 warps (13.8/SM), 2x the
// latency-hiding at identical traffic.
//
// per (n,d): sigma2_t = omega_d + sigma2_{t-1} * (alpha_d*z_{t-1}^2 + beta_d)
//            x_t = mu_d + sqrt(max(sigma2_t, 1e-12)) * z_t
// (sigma2 >= omega > 0 here, so the carried value needs no clamp; clamp only
//  feeds the sqrt.)

#define GARCH_N 32768
#define GARCH_T 2048
#define GARCH_D 2
#define ROW_BYTES (GARCH_T * GARCH_D * 4)   // 16384 bytes per chain-row (n)

#define CHN     16                 // n-chains per CTA (32 threads = 16n x 2d)
#define TC      16                 // timesteps per stage
#define CHUNK   (TC * GARCH_D * 4) // 128 bytes per n-chain per stage
#define NSTAGE  (GARCH_T / TC)     // 128 stages
#define DEPTH   5                  // input ring depth
#define NROUND  (CHN * 8 / 32)     // 4 cooperative 16B rounds per tile

#define TILE_W  (CHN * CHUNK)                    // 2 KB per tile
#define SMEM_BYTES (TILE_W * (DEPTH + 2))        // 5 in + 2 out = 14 KB

__device__ __forceinline__ float sqapx(float x) {
    float r; asm("sqrt.approx.f32 %0, %1;" : "=f"(r) : "f"(x)); return r;
}

// offset of (n-chain c, 16B-chunk j) within a 2KB tile.
// XOR-8 swizzle: conflict-free for the cooperative sweep (8 lanes, fixed c,
// j=lane&7) and for the compute sweep (fixed j; distinct c -> distinct banks,
// lane pairs read the same address = broadcast).
__device__ __forceinline__ int swz(int c, int j) {
    return c * CHUNK + ((j ^ (c & 7)) << 4);
}

__device__ __forceinline__ void cp_async16(char* smem_dst, const char* gsrc) {
    unsigned saddr = (unsigned)__cvta_generic_to_shared(smem_dst);
    asm volatile("cp.async.cg.shared.global [%0], [%1], 16;\n"
                 :: "r"(saddr), "l"(gsrc));
}
__device__ __forceinline__ void cp_commit() {
    asm volatile("cp.async.commit_group;\n");
}
__device__ __forceinline__ void cp_wait() {
    asm volatile("cp.async.wait_group %0;\n" :: "n"(DEPTH - 1));
}

__global__ void __launch_bounds__(32, 14)
garch_kernel(const float* __restrict__ z,
             const float* __restrict__ omega,
             const float* __restrict__ alpha,
             const float* __restrict__ beta,
             const float* __restrict__ mu,
             const float* __restrict__ sigma2_0,
             float* __restrict__ x)
{
    extern __shared__ char smem[];
    const int l  = threadIdx.x;             // lane
    const int cc = l >> 1;                  // compute: my n-chain (0..15)
    const int d  = l & 1;                   // compute: my dimension

    char* wbase = smem;
    char* outb0 = wbase + DEPTH * TILE_W;
    char* outb1 = outb0 + TILE_W;

    const size_t chain_base = (size_t)blockIdx.x * CHN;
    const char* zg = (const char*)z + chain_base * ROW_BYTES;
    char*       xg = (char*)x       + chain_base * ROW_BYTES;

    // cooperative mapping: round k (0..3): chunkid = l + 32k
    //   n-chain tc = chunkid>>3 ; 16B-chunk jj = l&7 (fixed per lane)
    // 8 consecutive lanes cover one chain's contiguous 128B (one line).
    const int jj = l & 7;

    // ---- prologue: fill DEPTH input tiles; group g <-> tile g ----
#pragma unroll
    for (int sp = 0; sp < DEPTH; sp++) {
        char* dst = wbase + sp * TILE_W;
#pragma unroll
        for (int k = 0; k < NROUND; k++) {
            int tc = (l + 32 * k) >> 3;
            cp_async16(dst + swz(tc, jj),
                       zg + (size_t)tc * ROW_BYTES + sp * CHUNK + jj * 16);
        }
        cp_commit();
    }

    // ---- scalar per-(n,d) recurrence state ----
    const float om = omega[d];
    const float al = alpha[d];
    const float be = beta[d];
    const float m  = mu[d];
    float s2 = sigma2_0[d];
    float fc = be;

    for (int s = 0; s < NSTAGE; s++) {
        // ---- prefetch tile s+DEPTH-1 into ring slot freed at iter s-1 ----
        if (s > 0) {
            const int sp = s + DEPTH - 1;
            if (sp < NSTAGE) {
                char* dst = wbase + (sp % DEPTH) * TILE_W;
#pragma unroll
                for (int k = 0; k < NROUND; k++) {
                    int tc = (l + 32 * k) >> 3;
                    cp_async16(dst + swz(tc, jj),
                               zg + (size_t)tc * ROW_BYTES + (size_t)sp * CHUNK + jj * 16);
                }
            }
            cp_commit();   // always commit: keeps group<->tile accounting exact
        }

        // ---- cooperative coalesced store of out tile s-1 ----
        if (s > 0) {
            const char* ob = ((s - 1) & 1) ? outb1 : outb0;
            const size_t tbase = (size_t)(s - 1) * CHUNK;
#pragma unroll
            for (int k = 0; k < NROUND; k++) {
                int tc = (l + 32 * k) >> 3;
                const float4 v = *(const float4*)(ob + swz(tc, jj));
                *(float4*)(xg + (size_t)tc * ROW_BYTES + tbase + jj * 16) = v;
            }
        }

        // Groups committed so far: DEPTH + s (tail commits may be empty and
        // complete instantly). pending<=DEPTH-1 => tile s complete.
        cp_wait();
        __syncwarp();   // cp.async data visible warp-wide

        // ---- compute 16 timesteps for this thread's (n,d) chain ----
        const char* ib = wbase + (s % DEPTH) * TILE_W;
        char* ob = (s & 1) ? outb1 : outb0;
#pragma unroll
        for (int j = 0; j < 8; j++) {
            // chunk j of my chain row: [z(2j,0), z(2j,1), z(2j+1,0), z(2j+1,1)]
            // lane pair (2cc, 2cc+1) reads the same address -> smem broadcast.
            const float4 za = *(const float4*)(ib + swz(cc, j));
            const float z0 = d ? za.y : za.x;   // t = 2j,   dim d
            const float z1 = d ? za.w : za.z;   // t = 2j+1, dim d

            // step t = 2j
            s2 = fmaf(s2, fc, om);              // whole serial chain
            const float c0 = fmaxf(s2, 1e-12f);
            fc = fmaf(al, z0 * z0, be);
            const float x0 = fmaf(sqapx(c0), z0, m);

            // step t = 2j+1
            s2 = fmaf(s2, fc, om);
            const float c1 = fmaxf(s2, 1e-12f);
            fc = fmaf(al, z1 * z1, be);
            const float x1 = fmaf(sqapx(c1), z1, m);

            // both values land inside 16B-chunk j of my chain's out row:
            //   byte (t&1)*8 + d*4 within the chunk
            char* base = ob + swz(cc, j);
            *(float*)(base + d * 4)     = x0;
            *(float*)(base + 8 + d * 4) = x1;
        }

        __syncwarp();   // out tile s complete before iter s+1 reads it
    }

    // ---- epilogue: store the final out tile ----
    {
        const char* ob = ((NSTAGE - 1) & 1) ? outb1 : outb0;
        const size_t tbase = (size_t)(NSTAGE - 1) * CHUNK;
#pragma unroll
        for (int k = 0; k < NROUND; k++) {
            int tc = (l + 32 * k) >> 3;
            const float4 v = *(const float4*)(ob + swz(tc, jj));
            *(float4*)(xg + (size_t)tc * ROW_BYTES + tbase + jj * 16) = v;
        }
    }
}

extern "C" void kernel_launch(void* const* d_in, const int* in_sizes, int n_in,
                              void* d_out, int out_size)
{
    const float* z        = (const float*)d_in[0];
    const float* omega    = (const float*)d_in[1];
    const float* alpha    = (const float*)d_in[2];
    const float* beta     = (const float*)d_in[3];
    const float* mu       = (const float*)d_in[4];
    const float* sigma2_0 = (const float*)d_in[5];
    float* x = (float*)d_out;

    cudaFuncSetAttribute(garch_kernel,
                         cudaFuncAttributeMaxDynamicSharedMemorySize, SMEM_BYTES);

    const int blocks = GARCH_N / CHN;   // 2048 single-warp CTAs
    garch_kernel<<<blocks, 32, SMEM_BYTES>>>(z, omega, alpha, beta, mu, sigma2_0, x);
}

// round 12
// speedup vs baseline: 1.0528x; 1.0266x over previous
#include <cuda_runtime.h>
#include <cstdint>

// GARCH(1,1) path generation — single-warp CTAs, warp-autonomous pipelines,
// L2::256B prefetch on the read stream.
//
// R1 private rows: L1tex wavefront bound (302us). R3 CTA smem staging: 254us.
// R5 warp-autonomous rings: 204us. R6 CTA==warp, TC=16, DEPTH=5: 195us,
// DRAM 71%. R7 TC=32 regressed (bursty). R8 off-chain clamp: neutral.
// R9 scalar (n,d) chains, 2x occupancy: neutral -> NOT latency-bound; all
// shapes converge at 5.4-5.6 TB/s => DRAM mixed r/w efficiency ceiling.
// R11: cp.async .L2::256B prefetch -> DRAM sees 256B same-page read pairs,
// next stage's line hits L2; read request count to DRAM halves.
//
// sigma2_t = omega + sigma2_{t-1} * (alpha*z_{t-1}^2 + beta)
// x_t = mu + sqrt(max(sigma2_t, 1e-12)) * z_t
// (sigma2 >= omega > 0 here, so the carried value needs no clamp; clamp only
//  feeds the sqrt.)

#define GARCH_N 32768
#define GARCH_T 2048
#define GARCH_D 2
#define ROW_BYTES (GARCH_T * GARCH_D * 4)   // 16384 bytes per chain

#define CH      32                 // chains per CTA (= threads = 1 warp)
#define TC      16                 // timesteps per stage
#define CHUNK   (TC * GARCH_D * 4) // 128 bytes per chain per stage
#define NSTAGE  (GARCH_T / TC)     // 128 stages
#define DEPTH   5                  // input ring depth

#define TILE_W  (CH * CHUNK)                     // 4 KB per tile
#define SMEM_BYTES (TILE_W * (DEPTH + 2))        // 5 in + 2 out = 28 KB

typedef unsigned long long u64;

__device__ __forceinline__ u64 pk2(float lo, float hi) {
    u64 r; asm("mov.b64 %0, {%1, %2};" : "=l"(r) : "f"(lo), "f"(hi)); return r;
}
__device__ __forceinline__ void upk2(u64 v, float& lo, float& hi) {
    asm("mov.b64 {%0, %1}, %2;" : "=f"(lo), "=f"(hi) : "l"(v));
}
__device__ __forceinline__ u64 fma2(u64 a, u64 b, u64 c) {
    u64 r; asm("fma.rn.f32x2 %0, %1, %2, %3;" : "=l"(r) : "l"(a), "l"(b), "l"(c)); return r;
}
__device__ __forceinline__ u64 mul2(u64 a, u64 b) {
    u64 r; asm("mul.rn.f32x2 %0, %1, %2;" : "=l"(r) : "l"(a), "l"(b)); return r;
}
__device__ __forceinline__ float sqapx(float x) {
    float r; asm("sqrt.approx.f32 %0, %1;" : "=f"(r) : "f"(x)); return r;
}

// offset of (local chain c, 16B-chunk j) within a 4KB tile.
// XOR-8 swizzle: conflict-free for both the per-chain access (fixed c,
// j=0..7) and the cooperative access (8 lanes sweep the row of one c).
__device__ __forceinline__ int swz(int c, int j) {
    return c * CHUNK + ((j ^ (c & 7)) << 4);
}

// cp.async with L2::256B prefetch: also pulls the adjacent 128B line of the
// same row into L2 (consumed by the next stage) -> 256B same-page DRAM bursts.
__device__ __forceinline__ void cp_async16(char* smem_dst, const char* gsrc) {
    unsigned saddr = (unsigned)__cvta_generic_to_shared(smem_dst);
    asm volatile("cp.async.cg.shared.global.L2::256B [%0], [%1], 16;\n"
                 :: "r"(saddr), "l"(gsrc));
}
__device__ __forceinline__ void cp_commit() {
    asm volatile("cp.async.commit_group;\n");
}
__device__ __forceinline__ void cp_wait() {
    asm volatile("cp.async.wait_group %0;\n" :: "n"(DEPTH - 1));
}

__global__ void __launch_bounds__(CH, 8)
garch_kernel(const float* __restrict__ z,
             const float* __restrict__ omega,
             const float* __restrict__ alpha,
             const float* __restrict__ beta,
             const float* __restrict__ mu,
             const float* __restrict__ sigma2_0,
             float* __restrict__ x)
{
    extern __shared__ char smem[];
    const int l = threadIdx.x;              // lane

    char* wbase = smem;
    char* outb0 = wbase + DEPTH * TILE_W;
    char* outb1 = outb0 + TILE_W;

    const size_t chain_base = (size_t)blockIdx.x * CH;
    const char* zg = (const char*)z + chain_base * ROW_BYTES;
    char*       xg = (char*)x       + chain_base * ROW_BYTES;

    // warp-internal cooperative mapping: round k (0..7):
    //   chunkid = l + 32k ; local chain c = chunkid>>3 ; j = l&7 (fixed)
    // 8 consecutive lanes cover one chain's contiguous 128B (one line).
    const int jj = l & 7;

    // ---- prologue: fill DEPTH input tiles; group g <-> tile g ----
#pragma unroll
    for (int sp = 0; sp < DEPTH; sp++) {
        char* dst = wbase + sp * TILE_W;
#pragma unroll
        for (int k = 0; k < 8; k++) {
            int c = (l + 32 * k) >> 3;
            cp_async16(dst + swz(c, jj),
                       zg + (size_t)c * ROW_BYTES + sp * CHUNK + jj * 16);
        }
        cp_commit();
    }

    // ---- per-chain recurrence state ----
    const u64 om2 = pk2(omega[0], omega[1]);
    const u64 al2 = pk2(alpha[0], alpha[1]);
    const u64 be2 = pk2(beta[0], beta[1]);
    const float m0 = mu[0], m1 = mu[1];
    u64 s2 = pk2(sigma2_0[0], sigma2_0[1]);
    u64 fc = be2;

    for (int s = 0; s < NSTAGE; s++) {
        // ---- prefetch tile s+DEPTH-1 into ring slot freed at iter s-1 ----
        if (s > 0) {
            const int sp = s + DEPTH - 1;
            if (sp < NSTAGE) {
                char* dst = wbase + (sp % DEPTH) * TILE_W;
#pragma unroll
                for (int k = 0; k < 8; k++) {
                    int c = (l + 32 * k) >> 3;
                    cp_async16(dst + swz(c, jj),
                               zg + (size_t)c * ROW_BYTES + (size_t)sp * CHUNK + jj * 16);
                }
            }
            cp_commit();   // always commit: keeps group<->tile accounting exact
        }

        // ---- cooperative coalesced store of out tile s-1 ----
        if (s > 0) {
            const char* ob = ((s - 1) & 1) ? outb1 : outb0;
            const size_t tbase = (size_t)(s - 1) * CHUNK;
#pragma unroll
            for (int k = 0; k < 8; k++) {
                int c = (l + 32 * k) >> 3;
                const float4 v = *(const float4*)(ob + swz(c, jj));
                *(float4*)(xg + (size_t)c * ROW_BYTES + tbase + jj * 16) = v;
            }
        }

        // Groups committed so far: DEPTH + s (tail commits may be empty and
        // complete instantly). pending<=DEPTH-1 => tile s complete.
        cp_wait();
        __syncwarp();   // make lane-X cp.async data visible warp-wide

        // ---- compute 16 timesteps for this thread's chain (= lane l) ----
        const char* ib = wbase + (s % DEPTH) * TILE_W;
        char* ob = (s & 1) ? outb1 : outb0;
#pragma unroll
        for (int j = 0; j < 8; j++) {
            const float4 za = *(const float4*)(ib + swz(l, j));
            float4 xa;
#define GSTEP(z0, z1, o0, o1)                                        \
            {                                                        \
                s2 = fma2(s2, fc, om2);  /* whole serial chain */    \
                float lo, hi;                                        \
                upk2(s2, lo, hi);                                    \
                const float clo = fmaxf(lo, 1e-12f);                 \
                const float chi = fmaxf(hi, 1e-12f);                 \
                const u64 zz = pk2(z0, z1);                          \
                fc = fma2(al2, mul2(zz, zz), be2);                   \
                o0 = fmaf(sqapx(clo), (z0), m0);                     \
                o1 = fmaf(sqapx(chi), (z1), m1);                     \
            }
            GSTEP(za.x, za.y, xa.x, xa.y)
            GSTEP(za.z, za.w, xa.z, xa.w)
#undef GSTEP
            *(float4*)(ob + swz(l, j)) = xa;
        }

        __syncwarp();   // out tile s complete before iter s+1 reads it
    }

    // ---- epilogue: store the final out tile ----
    {
        const char* ob = ((NSTAGE - 1) & 1) ? outb1 : outb0;
        const size_t tbase = (size_t)(NSTAGE - 1) * CHUNK;
#pragma unroll
        for (int k = 0; k < 8; k++) {
            int c = (l + 32 * k) >> 3;
            const float4 v = *(const float4*)(ob + swz(c, jj));
            *(float4*)(xg + (size_t)c * ROW_BYTES + tbase + jj * 16) = v;
        }
    }
}

extern "C" void kernel_launch(void* const* d_in, const int* in_sizes, int n_in,
                              void* d_out, int out_size)
{
    const float* z        = (const float*)d_in[0];
    const float* omega    = (const float*)d_in[1];
    const float* alpha    = (const float*)d_in[2];
    const float* beta     = (const float*)d_in[3];
    const float* mu       = (const float*)d_in[4];
    const float* sigma2_0 = (const float*)d_in[5];
    float* x = (float*)d_out;

    cudaFuncSetAttribute(garch_kernel,
                         cudaFuncAttributeMaxDynamicSharedMemorySize, SMEM_BYTES);

    const int blocks = GARCH_N / CH;   // 1024 single-warp CTAs
    garch_kernel<<<blocks, CH, SMEM_BYTES>>>(z, omega, alpha, beta, mu, sigma2_0, x);
}